// round 15
// baseline (speedup 1.0000x reference)
#include <cuda_runtime.h>

#define PLANEW   1090            // u64 words per plane: 34*32=1088 +2; 1090 % 16 == 2
#define NTHREADS 256
#define PI_F     3.14159265358979323846f

typedef unsigned long long u64;

// ---- packed f32x2 helpers (sm_100+ PTX; ptxas never emits these from C++) ----
__device__ __forceinline__ u64 pk(float a, float b) {
    u64 r; asm("mov.b64 %0, {%1, %2};" : "=l"(r) : "f"(a), "f"(b)); return r;
}
__device__ __forceinline__ float2 upk(u64 v) {
    float2 r; asm("mov.b64 {%0, %1}, %2;" : "=f"(r.x), "=f"(r.y) : "l"(v)); return r;
}
__device__ __forceinline__ u64 swp(u64 v) {
    u64 r;
    asm("{\n\t.reg .b32 lo, hi;\n\tmov.b64 {lo, hi}, %1;\n\tmov.b64 %0, {hi, lo};\n\t}"
        : "=l"(r) : "l"(v));
    return r;
}
__device__ __forceinline__ u64 f2add(u64 a, u64 b) {
    u64 r; asm("add.rn.f32x2 %0, %1, %2;" : "=l"(r) : "l"(a), "l"(b)); return r;
}
__device__ __forceinline__ u64 f2sub(u64 a, u64 b) {
    u64 r; asm("sub.rn.f32x2 %0, %1, %2;" : "=l"(r) : "l"(a), "l"(b)); return r;
}
__device__ __forceinline__ u64 f2mul(u64 a, u64 b) {
    u64 r; asm("mul.rn.f32x2 %0, %1, %2;" : "=l"(r) : "l"(a), "l"(b)); return r;
}
__device__ __forceinline__ u64 f2fma(u64 a, u64 b, u64 c) {
    u64 r; asm("fma.rn.f32x2 %0, %1, %2, %3;" : "=l"(r) : "l"(a), "l"(b), "l"(c)); return r;
}
__device__ __forceinline__ u64 cmul(u64 d, u64 wcc, u64 wss) {
    return f2fma(swp(d), wss, f2mul(d, wcc));
}
// complex square: (c + i s)^2 = (c^2 - s^2, 2cs)
__device__ __forceinline__ void csq(float& oc, float& os, float c, float s) {
    oc = fmaf(c, c, -s * s);
    os = 2.0f * c * s;
}

__device__ __constant__ float C16c[16] = {
    1.0f, 0.980785280403230449f, 0.923879532511286756f, 0.831469612302545237f,
    0.707106781186547524f, 0.555570233019602225f, 0.382683432365089772f,
    0.195090322016128268f, 0.0f, -0.195090322016128268f, -0.382683432365089772f,
    -0.555570233019602225f, -0.707106781186547524f, -0.831469612302545237f,
    -0.923879532511286756f, -0.980785280403230449f};
__device__ __constant__ float S16c[16] = {
    0.0f, 0.195090322016128268f, 0.382683432365089772f, 0.555570233019602225f,
    0.707106781186547524f, 0.831469612302545237f, 0.923879532511286756f,
    0.980785280403230449f, 1.0f, 0.980785280403230449f, 0.923879532511286756f,
    0.831469612302545237f, 0.707106781186547524f, 0.555570233019602225f,
    0.382683432365089772f, 0.195090322016128268f};

// radix-2 stage with PRECOMPUTED base twiddle w0 (non-constant stages).
// Pairs (j, j+H); k-th twiddle = w0 * e^{∓i*pi*k/H} via constant rotation.
template<int H, bool INV>
__device__ __forceinline__ void bf32_pre(u64* X, float w0c, float w0s) {
    #pragma unroll
    for (int k = 0; k < H; ++k) {
        const int t = k * (16 / H);
        const float ckr = C16c[t];
        const float cki = INV ? S16c[t] : -S16c[t];
        const float wc = w0c * ckr - w0s * cki;
        const float ws = w0s * ckr + w0c * cki;
        const u64 wcc = pk(wc, wc);
        const u64 wss = pk(-ws, ws);
        #pragma unroll
        for (int g = 0; g < 32 / (2 * H); ++g) {
            const int j  = g * 2 * H + k;
            const int j2 = j + H;
            if (!INV) {
                u64 s = f2add(X[j], X[j2]);
                u64 d = f2sub(X[j], X[j2]);
                X[j]  = s;
                X[j2] = cmul(d, wcc, wss);
            } else {
                u64 tt = cmul(X[j2], wcc, wss);
                X[j2] = f2sub(X[j], tt);
                X[j]  = f2add(X[j], tt);
            }
        }
    }
}

// constant-twiddle stage (base_eff == 0), used in phase C.
template<int H, bool INV>
__device__ __forceinline__ void bf32_c(u64* X) {
    #pragma unroll
    for (int k = 0; k < H; ++k) {
        const int t = k * (16 / H);
        const float wc = C16c[t];
        const float ws = INV ? S16c[t] : -S16c[t];
        const u64 wcc = pk(wc, wc);
        const u64 wss = pk(-ws, ws);
        #pragma unroll
        for (int g = 0; g < 32 / (2 * H); ++g) {
            const int j  = g * 2 * H + k;
            const int j2 = j + H;
            if (!INV) {
                u64 s = f2add(X[j], X[j2]);
                u64 d = f2sub(X[j], X[j2]);
                X[j] = s;
                if (t == 0)      X[j2] = d;
                else if (t == 8) X[j2] = f2mul(swp(d), pk(1.0f, -1.0f));   // w = -i
                else             X[j2] = cmul(d, wcc, wss);
            } else {
                u64 tt;
                if (t == 0)      tt = X[j2];
                else if (t == 8) tt = f2mul(swp(X[j2]), pk(-1.0f, 1.0f)); // w = +i
                else             tt = cmul(X[j2], wcc, wss);
                X[j2] = f2sub(X[j], tt);
                X[j]  = f2add(X[j], tt);
            }
        }
    }
}

// first forward stage (H=16) with X[16..31] == 0: X[k+16] = X[k] * w_k
__device__ __forceinline__ void bf32_first(u64* X, float w0c, float w0s) {
    #pragma unroll
    for (int k = 0; k < 16; ++k) {
        const float ckr = C16c[k];
        const float cki = -S16c[k];
        const float wc = w0c * ckr - w0s * cki;
        const float ws = w0s * ckr + w0c * cki;
        X[k + 16] = cmul(X[k], pk(wc, wc), pk(-ws, ws));
    }
}

// last inverse stage (H=16): only X[0..15] survive
__device__ __forceinline__ void bf32_last(u64* X, float w0c, float w0s) {
    #pragma unroll
    for (int k = 0; k < 16; ++k) {
        const float ckr = C16c[k];
        const float cki = S16c[k];
        const float wc = w0c * ckr - w0s * cki;
        const float ws = w0s * ckr + w0c * cki;
        u64 tt = cmul(X[k + 16], pk(wc, wc), pk(-ws, ws));
        X[k] = f2add(X[k], tt);
    }
}

// One CTA = one tile: 8 packed complex rows (real rows bi, bi+4096;
// bi = bc*512 + a0 + row).  Phase A/A2 mapping rowL=tid&7, rL=tid>>3 (warp
// global ops = 4 full 32B sectors); 20 stages in registers; TWO smem
// transposes.  Independent long-latency work (filter LDG, inverse twiddle
// chain) is issued BEFORE each __syncthreads so it overlaps barrier wait.
// Base twiddles per phase come from ONE sincos + 4 complex squarings
// (w for stride S/2 = (w for stride S)^2, exact).
// Plane layout word(p) = 34*(p>>5) + (p&31):
//   A access: word = rowL*PLANEW + rL + 34j   (LDS/STS.64, conflict-free)
//   C access: word = w*PLANEW + 34r + j       (LDS/STS.128, conflict-free)
__global__ void __launch_bounds__(NTHREADS, 2)
fbp_kernel(const float* __restrict__ x, const float* __restrict__ filt,
           float* __restrict__ out)
{
    extern __shared__ float2 sm2[];
    u64* __restrict__ sm = reinterpret_cast<u64*>(sm2);

    const int tid = threadIdx.x;
    const int bc  = blockIdx.x >> 6;         // 0..7
    const int a0  = (blockIdx.x & 63) << 3;  // 0..504 step 8

    const int rowL = tid & 7;    // a-offset within tile
    const int rL   = tid >> 3;   // 0..31
    const int bAL  = rowL * PLANEW + rL;     // + 34j
    const int w    = tid >> 5;
    const int r    = tid & 31;
    const int bC   = w * PLANEW + 34 * r;    // 16B aligned (34r even)

    u64 X[32];

    // forward base-twiddle chain: wf[i] = e^{-i*pi*rL/(512 >> i)}, i=0..4
    float wfc[5], wfs[5];
    __sincosf(-PI_F * (float)rL * (1.0f / 512.0f), &wfs[0], &wfc[0]);
    #pragma unroll
    for (int i = 1; i < 5; ++i) csq(wfc[i], wfs[i], wfc[i-1], wfs[i-1]);

    // ======== phase A: direct global load + fwd strides 512..32 ========
    {
        const float* __restrict__ xre = x + bc * 262144 + a0 + rowL;
        const float* __restrict__ xim = x + (bc + 8) * 262144 + a0 + rowL;
        #pragma unroll
        for (int j = 0; j < 16; ++j) {   // p = rL + 32j < 512
            float vr = __ldg(xre + (rL + 32 * j) * 512);
            float vi = __ldg(xim + (rL + 32 * j) * 512);
            X[j] = pk(vr, vi);
        }
    }
    bf32_first(X, wfc[0], wfs[0]);
    bf32_pre<8, false>(X, wfc[1], wfs[1]);
    bf32_pre<4, false>(X, wfc[2], wfs[2]);
    bf32_pre<2, false>(X, wfc[3], wfs[3]);
    bf32_pre<1, false>(X, wfc[4], wfs[4]);
    #pragma unroll
    for (int j = 0; j < 32; ++j) sm[bAL + 34 * j] = X[j];

    // filter loads issued BEFORE the barrier: latency overlaps barrier wait
    float4 f0, f1, f2, f3, f4v, f5, f6, f7;
    {
        const float4* __restrict__ fp = reinterpret_cast<const float4*>(filt + 32 * r);
        f0 = __ldg(fp + 0); f1 = __ldg(fp + 1); f2 = __ldg(fp + 2); f3 = __ldg(fp + 3);
        f4v = __ldg(fp + 4); f5 = __ldg(fp + 5); f6 = __ldg(fp + 6); f7 = __ldg(fp + 7);
    }
    __syncthreads();

    // ======== phase C: fwd 16..1, filter, inv 1..16 ========
    {
        const ulonglong2* __restrict__ cp =
            reinterpret_cast<const ulonglong2*>(sm + bC);
        #pragma unroll
        for (int h = 0; h < 16; ++h) {
            ulonglong2 v = cp[h];
            X[2*h] = v.x; X[2*h+1] = v.y;
        }
    }
    bf32_c<16, false>(X);
    bf32_c< 8, false>(X);
    bf32_c< 4, false>(X);
    bf32_c< 2, false>(X);
    bf32_c< 1, false>(X);
    {
        const float4 ff[8] = {f0, f1, f2, f3, f4v, f5, f6, f7};
        #pragma unroll
        for (int i = 0; i < 8; ++i) {   // bit-reversed-domain filter; fold 1/n
            X[4*i+0] = f2mul(X[4*i+0], pk(ff[i].x*(1.0f/1024.0f), ff[i].x*(1.0f/1024.0f)));
            X[4*i+1] = f2mul(X[4*i+1], pk(ff[i].y*(1.0f/1024.0f), ff[i].y*(1.0f/1024.0f)));
            X[4*i+2] = f2mul(X[4*i+2], pk(ff[i].z*(1.0f/1024.0f), ff[i].z*(1.0f/1024.0f)));
            X[4*i+3] = f2mul(X[4*i+3], pk(ff[i].w*(1.0f/1024.0f), ff[i].w*(1.0f/1024.0f)));
        }
    }
    bf32_c< 1, true>(X);
    bf32_c< 2, true>(X);
    bf32_c< 4, true>(X);
    bf32_c< 8, true>(X);
    bf32_c<16, true>(X);
    {
        ulonglong2* __restrict__ cp = reinterpret_cast<ulonglong2*>(sm + bC);
        #pragma unroll
        for (int h = 0; h < 16; ++h) {
            ulonglong2 v; v.x = X[2*h]; v.y = X[2*h+1];
            cp[h] = v;
        }
    }

    // inverse base-twiddle chain BEFORE the barrier (overlaps barrier wait)
    float wic[5], wis[5];
    __sincosf(PI_F * (float)rL * (1.0f / 512.0f), &wis[0], &wic[0]);
    #pragma unroll
    for (int i = 1; i < 5; ++i) csq(wic[i], wis[i], wic[i-1], wis[i-1]);
    __syncthreads();

    // ======== phase A2: inv strides 32..512 + direct global store ========
    #pragma unroll
    for (int j = 0; j < 32; ++j) X[j] = sm[bAL + 34 * j];
    bf32_pre<1, true>(X, wic[4], wis[4]);
    bf32_pre<2, true>(X, wic[3], wis[3]);
    bf32_pre<4, true>(X, wic[2], wis[2]);
    bf32_pre<8, true>(X, wic[1], wis[1]);
    bf32_last(X, wic[0], wis[0]);
    {
        // emit p = rL + 32j, j<16: out[p*8192 + bi], imag at bi+4096
        float* __restrict__ ore = out + bc * 512 + a0 + rowL;
        float* __restrict__ oim = out + (bc + 8) * 512 + a0 + rowL;
        #pragma unroll
        for (int j = 0; j < 16; ++j) {
            float2 v = upk(X[j]);
            ore[(rL + 32 * j) * 8192] = v.x;
            oim[(rL + 32 * j) * 8192] = v.y;
        }
    }
}

extern "C" void kernel_launch(void* const* d_in, const int* in_sizes, int n_in,
                              void* d_out, int out_size) {
    (void)in_sizes; (void)n_in; (void)out_size;
    const float* x    = (const float*)d_in[0];
    const float* filt = (const float*)d_in[3];   // fourier_filter_br
    float* out = (float*)d_out;

    const size_t smem_bytes = (size_t)8 * PLANEW * sizeof(u64);  // 69760
    cudaFuncSetAttribute(fbp_kernel, cudaFuncAttributeMaxDynamicSharedMemorySize,
                         (int)smem_bytes);
    fbp_kernel<<<512, NTHREADS, smem_bytes>>>(x, filt, out);
}

// round 16
// speedup vs baseline: 1.0122x; 1.0122x over previous
#include <cuda_runtime.h>

#define PLANEW   1090            // u64 words per plane: 34*32=1088 +2; 1090 % 16 == 2
#define NTHREADS 256
#define PI_F     3.14159265358979323846f

typedef unsigned long long u64;

// ---- packed f32x2 helpers (sm_100+ PTX; ptxas never emits these from C++) ----
__device__ __forceinline__ u64 pk(float a, float b) {
    u64 r; asm("mov.b64 %0, {%1, %2};" : "=l"(r) : "f"(a), "f"(b)); return r;
}
__device__ __forceinline__ float2 upk(u64 v) {
    float2 r; asm("mov.b64 {%0, %1}, %2;" : "=f"(r.x), "=f"(r.y) : "l"(v)); return r;
}
__device__ __forceinline__ u64 swp(u64 v) {
    u64 r;
    asm("{\n\t.reg .b32 lo, hi;\n\tmov.b64 {lo, hi}, %1;\n\tmov.b64 %0, {hi, lo};\n\t}"
        : "=l"(r) : "l"(v));
    return r;
}
__device__ __forceinline__ u64 f2add(u64 a, u64 b) {
    u64 r; asm("add.rn.f32x2 %0, %1, %2;" : "=l"(r) : "l"(a), "l"(b)); return r;
}
__device__ __forceinline__ u64 f2sub(u64 a, u64 b) {
    u64 r; asm("sub.rn.f32x2 %0, %1, %2;" : "=l"(r) : "l"(a), "l"(b)); return r;
}
__device__ __forceinline__ u64 f2mul(u64 a, u64 b) {
    u64 r; asm("mul.rn.f32x2 %0, %1, %2;" : "=l"(r) : "l"(a), "l"(b)); return r;
}
__device__ __forceinline__ u64 f2fma(u64 a, u64 b, u64 c) {
    u64 r; asm("fma.rn.f32x2 %0, %1, %2, %3;" : "=l"(r) : "l"(a), "l"(b), "l"(c)); return r;
}
__device__ __forceinline__ u64 cmul(u64 d, u64 wcc, u64 wss) {
    return f2fma(swp(d), wss, f2mul(d, wcc));
}

__device__ __constant__ float C16c[16] = {
    1.0f, 0.980785280403230449f, 0.923879532511286756f, 0.831469612302545237f,
    0.707106781186547524f, 0.555570233019602225f, 0.382683432365089772f,
    0.195090322016128268f, 0.0f, -0.195090322016128268f, -0.382683432365089772f,
    -0.555570233019602225f, -0.707106781186547524f, -0.831469612302545237f,
    -0.923879532511286756f, -0.980785280403230449f};
__device__ __constant__ float S16c[16] = {
    0.0f, 0.195090322016128268f, 0.382683432365089772f, 0.555570233019602225f,
    0.707106781186547524f, 0.831469612302545237f, 0.923879532511286756f,
    0.980785280403230449f, 1.0f, 0.980785280403230449f, 0.923879532511286756f,
    0.831469612302545237f, 0.707106781186547524f, 0.555570233019602225f,
    0.382683432365089772f, 0.195090322016128268f};

// radix-2 stage with PRECOMPUTED base twiddle w0 (non-constant stages).
// Pairs (j, j+H); k-th twiddle = w0 * e^{∓i*pi*k/H} via constant rotation.
template<int H, bool INV>
__device__ __forceinline__ void bf32_pre(u64* X, float w0c, float w0s) {
    #pragma unroll
    for (int k = 0; k < H; ++k) {
        const int t = k * (16 / H);
        const float ckr = C16c[t];
        const float cki = INV ? S16c[t] : -S16c[t];
        const float wc = w0c * ckr - w0s * cki;
        const float ws = w0s * ckr + w0c * cki;
        const u64 wcc = pk(wc, wc);
        const u64 wss = pk(-ws, ws);
        #pragma unroll
        for (int g = 0; g < 32 / (2 * H); ++g) {
            const int j  = g * 2 * H + k;
            const int j2 = j + H;
            if (!INV) {
                u64 s = f2add(X[j], X[j2]);
                u64 d = f2sub(X[j], X[j2]);
                X[j]  = s;
                X[j2] = cmul(d, wcc, wss);
            } else {
                u64 tt = cmul(X[j2], wcc, wss);
                X[j2] = f2sub(X[j], tt);
                X[j]  = f2add(X[j], tt);
            }
        }
    }
}

// constant-twiddle stage (base_eff == 0), used in phase C.
template<int H, bool INV>
__device__ __forceinline__ void bf32_c(u64* X) {
    #pragma unroll
    for (int k = 0; k < H; ++k) {
        const int t = k * (16 / H);
        const float wc = C16c[t];
        const float ws = INV ? S16c[t] : -S16c[t];
        const u64 wcc = pk(wc, wc);
        const u64 wss = pk(-ws, ws);
        #pragma unroll
        for (int g = 0; g < 32 / (2 * H); ++g) {
            const int j  = g * 2 * H + k;
            const int j2 = j + H;
            if (!INV) {
                u64 s = f2add(X[j], X[j2]);
                u64 d = f2sub(X[j], X[j2]);
                X[j] = s;
                if (t == 0)      X[j2] = d;
                else if (t == 8) X[j2] = f2mul(swp(d), pk(1.0f, -1.0f));   // w = -i
                else             X[j2] = cmul(d, wcc, wss);
            } else {
                u64 tt;
                if (t == 0)      tt = X[j2];
                else if (t == 8) tt = f2mul(swp(X[j2]), pk(-1.0f, 1.0f)); // w = +i
                else             tt = cmul(X[j2], wcc, wss);
                X[j2] = f2sub(X[j], tt);
                X[j]  = f2add(X[j], tt);
            }
        }
    }
}

// first forward stage (H=16) with X[16..31] == 0: X[k+16] = X[k] * w_k
__device__ __forceinline__ void bf32_first(u64* X, float w0c, float w0s) {
    #pragma unroll
    for (int k = 0; k < 16; ++k) {
        const float ckr = C16c[k];
        const float cki = -S16c[k];
        const float wc = w0c * ckr - w0s * cki;
        const float ws = w0s * ckr + w0c * cki;
        X[k + 16] = cmul(X[k], pk(wc, wc), pk(-ws, ws));
    }
}

// last inverse stage (H=16): only X[0..15] survive
__device__ __forceinline__ void bf32_last(u64* X, float w0c, float w0s) {
    #pragma unroll
    for (int k = 0; k < 16; ++k) {
        const float ckr = C16c[k];
        const float cki = S16c[k];
        const float wc = w0c * ckr - w0s * cki;
        const float ws = w0s * ckr + w0c * cki;
        u64 tt = cmul(X[k + 16], pk(wc, wc), pk(-ws, ws));
        X[k] = f2add(X[k], tt);
    }
}

// One CTA = one tile: 8 packed complex rows (real rows bi, bi+4096;
// bi = bc*512 + a0 + row).  Phase A/A2 mapping rowL=tid&7, rL=tid>>3 (warp
// global ops = 4 full 32B sectors); 20 stages in registers; TWO smem
// transposes.  Long-latency independent work (filter LDG, next phase's base
// twiddles via 5 INDEPENDENT sincos — no error-amplifying chain) is issued
// BEFORE each __syncthreads so it overlaps the barrier wait.
// Plane layout word(p) = 34*(p>>5) + (p&31):
//   A access: word = rowL*PLANEW + rL + 34j   (LDS/STS.64, conflict-free)
//   C access: word = w*PLANEW + 34r + j       (LDS/STS.128, conflict-free)
__global__ void __launch_bounds__(NTHREADS, 2)
fbp_kernel(const float* __restrict__ x, const float* __restrict__ filt,
           float* __restrict__ out)
{
    extern __shared__ float2 sm2[];
    u64* __restrict__ sm = reinterpret_cast<u64*>(sm2);

    const int tid = threadIdx.x;
    const int bc  = blockIdx.x >> 6;         // 0..7
    const int a0  = (blockIdx.x & 63) << 3;  // 0..504 step 8

    const int rowL = tid & 7;    // a-offset within tile
    const int rL   = tid >> 3;   // 0..31
    const int bAL  = rowL * PLANEW + rL;     // + 34j
    const int w    = tid >> 5;
    const int r    = tid & 31;
    const int bC   = w * PLANEW + 34 * r;    // 16B aligned (34r even)

    u64 X[32];

    // forward base twiddles: wf[i] = e^{-i*pi*rL/(512>>i)} — 5 independent
    // sincos, issued up front so their latency overlaps the LDG burst.
    float wfc[5], wfs[5];
    const float frL = (float)rL;
    __sincosf(-PI_F * frL * (1.0f / 512.0f), &wfs[0], &wfc[0]);
    __sincosf(-PI_F * frL * (1.0f / 256.0f), &wfs[1], &wfc[1]);
    __sincosf(-PI_F * frL * (1.0f / 128.0f), &wfs[2], &wfc[2]);
    __sincosf(-PI_F * frL * (1.0f /  64.0f), &wfs[3], &wfc[3]);
    __sincosf(-PI_F * frL * (1.0f /  32.0f), &wfs[4], &wfc[4]);

    // ======== phase A: direct global load + fwd strides 512..32 ========
    {
        const float* __restrict__ xre = x + bc * 262144 + a0 + rowL;
        const float* __restrict__ xim = x + (bc + 8) * 262144 + a0 + rowL;
        #pragma unroll
        for (int j = 0; j < 16; ++j) {   // p = rL + 32j < 512
            float vr = __ldg(xre + (rL + 32 * j) * 512);
            float vi = __ldg(xim + (rL + 32 * j) * 512);
            X[j] = pk(vr, vi);
        }
    }
    bf32_first(X, wfc[0], wfs[0]);
    bf32_pre<8, false>(X, wfc[1], wfs[1]);
    bf32_pre<4, false>(X, wfc[2], wfs[2]);
    bf32_pre<2, false>(X, wfc[3], wfs[3]);
    bf32_pre<1, false>(X, wfc[4], wfs[4]);
    #pragma unroll
    for (int j = 0; j < 32; ++j) sm[bAL + 34 * j] = X[j];

    // filter loads issued BEFORE the barrier: latency overlaps barrier wait
    float4 f0, f1, f2, f3, f4v, f5, f6, f7;
    {
        const float4* __restrict__ fp = reinterpret_cast<const float4*>(filt + 32 * r);
        f0 = __ldg(fp + 0); f1 = __ldg(fp + 1); f2 = __ldg(fp + 2); f3 = __ldg(fp + 3);
        f4v = __ldg(fp + 4); f5 = __ldg(fp + 5); f6 = __ldg(fp + 6); f7 = __ldg(fp + 7);
    }
    __syncthreads();

    // ======== phase C: fwd 16..1, filter, inv 1..16 ========
    {
        const ulonglong2* __restrict__ cp =
            reinterpret_cast<const ulonglong2*>(sm + bC);
        #pragma unroll
        for (int h = 0; h < 16; ++h) {
            ulonglong2 v = cp[h];
            X[2*h] = v.x; X[2*h+1] = v.y;
        }
    }
    bf32_c<16, false>(X);
    bf32_c< 8, false>(X);
    bf32_c< 4, false>(X);
    bf32_c< 2, false>(X);
    bf32_c< 1, false>(X);
    {
        const float4 ff[8] = {f0, f1, f2, f3, f4v, f5, f6, f7};
        #pragma unroll
        for (int i = 0; i < 8; ++i) {   // bit-reversed-domain filter; fold 1/n
            X[4*i+0] = f2mul(X[4*i+0], pk(ff[i].x*(1.0f/1024.0f), ff[i].x*(1.0f/1024.0f)));
            X[4*i+1] = f2mul(X[4*i+1], pk(ff[i].y*(1.0f/1024.0f), ff[i].y*(1.0f/1024.0f)));
            X[4*i+2] = f2mul(X[4*i+2], pk(ff[i].z*(1.0f/1024.0f), ff[i].z*(1.0f/1024.0f)));
            X[4*i+3] = f2mul(X[4*i+3], pk(ff[i].w*(1.0f/1024.0f), ff[i].w*(1.0f/1024.0f)));
        }
    }
    bf32_c< 1, true>(X);
    bf32_c< 2, true>(X);
    bf32_c< 4, true>(X);
    bf32_c< 8, true>(X);
    bf32_c<16, true>(X);
    {
        ulonglong2* __restrict__ cp = reinterpret_cast<ulonglong2*>(sm + bC);
        #pragma unroll
        for (int h = 0; h < 16; ++h) {
            ulonglong2 v; v.x = X[2*h]; v.y = X[2*h+1];
            cp[h] = v;
        }
    }

    // inverse base twiddles BEFORE the barrier (5 independent sincos;
    // latency absorbed by the barrier wait, MUFU has ~96% idle headroom)
    float wic[5], wis[5];
    __sincosf(PI_F * frL * (1.0f / 512.0f), &wis[0], &wic[0]);
    __sincosf(PI_F * frL * (1.0f / 256.0f), &wis[1], &wic[1]);
    __sincosf(PI_F * frL * (1.0f / 128.0f), &wis[2], &wic[2]);
    __sincosf(PI_F * frL * (1.0f /  64.0f), &wis[3], &wic[3]);
    __sincosf(PI_F * frL * (1.0f /  32.0f), &wis[4], &wic[4]);
    __syncthreads();

    // ======== phase A2: inv strides 32..512 + direct global store ========
    #pragma unroll
    for (int j = 0; j < 32; ++j) X[j] = sm[bAL + 34 * j];
    bf32_pre<1, true>(X, wic[4], wis[4]);
    bf32_pre<2, true>(X, wic[3], wis[3]);
    bf32_pre<4, true>(X, wic[2], wis[2]);
    bf32_pre<8, true>(X, wic[1], wis[1]);
    bf32_last(X, wic[0], wis[0]);
    {
        // emit p = rL + 32j, j<16: out[p*8192 + bi], imag at bi+4096
        float* __restrict__ ore = out + bc * 512 + a0 + rowL;
        float* __restrict__ oim = out + (bc + 8) * 512 + a0 + rowL;
        #pragma unroll
        for (int j = 0; j < 16; ++j) {
            float2 v = upk(X[j]);
            ore[(rL + 32 * j) * 8192] = v.x;
            oim[(rL + 32 * j) * 8192] = v.y;
        }
    }
}

extern "C" void kernel_launch(void* const* d_in, const int* in_sizes, int n_in,
                              void* d_out, int out_size) {
    (void)in_sizes; (void)n_in; (void)out_size;
    const float* x    = (const float*)d_in[0];
    const float* filt = (const float*)d_in[3];   // fourier_filter_br
    float* out = (float*)d_out;

    const size_t smem_bytes = (size_t)8 * PLANEW * sizeof(u64);  // 69760
    cudaFuncSetAttribute(fbp_kernel, cudaFuncAttributeMaxDynamicSharedMemorySize,
                         (int)smem_bytes);
    fbp_kernel<<<512, NTHREADS, smem_bytes>>>(x, filt, out);
}